// round 14
// baseline (speedup 1.0000x reference)
#include <cuda_runtime.h>
#include <cstdint>
#include <math.h>

#define SIGMA_C 0.14f
#define R0_C    50.0f
#define DT_C    0.1f
#define NT_C    2000
#define B_C     4096

#define TABN   1024
#define NNODES (TABN + 2)
#define JMAX_C 3.5f
#define INVH_F ((float)TABN / JMAX_C)

#define T_FROZEN 112
#define TILE_S   32
#define NTILES_A ((NT_C - T_FROZEN) / TILE_S)    // 59
#define QLEN 272

__device__ float g_nodes[NNODES];

#define NODE_BLOCKS ((NNODES + 31) / 32)      // 33

__global__ void __launch_bounds__(128)
build_nodes_kernel(const float* __restrict__ W1, const float* __restrict__ b1,
                   const float* __restrict__ W2, const float* __restrict__ b2,
                   const float* __restrict__ W3, const float* __restrict__ b3) {
    const int tid = threadIdx.x;
    __shared__ float sW2[64 * 64];
    __shared__ float sh1[32][65];
    {
        const float4* src = reinterpret_cast<const float4*>(W2);
        float4* dst = reinterpret_cast<float4*>(sW2);
#pragma unroll
        for (int q = 0; q < 8; ++q) dst[tid + 128 * q] = __ldg(src + tid + 128 * q);
    }
    const int nl = tid >> 2, c = tid & 3;
    const int node = blockIdx.x * 32 + nl;
    const float x = (float)(node - 1) * (JMAX_C / (float)TABN);
#pragma unroll
    for (int k = 0; k < 16; ++k) {
        const int u = c * 16 + k;
        sh1[nl][u] = fmaxf(fmaf(x, __ldg(W1 + u), __ldg(b1 + u)), 0.0f);
    }
    __syncthreads();
    float acc[16];
#pragma unroll
    for (int k = 0; k < 16; ++k) acc[k] = __ldg(b2 + c * 16 + k);
#pragma unroll 4
    for (int j = 0; j < 64; ++j) {
        const float hj = sh1[nl][j];
        const float4* row = reinterpret_cast<const float4*>(sW2 + j * 64 + c * 16);
#pragma unroll
        for (int q = 0; q < 4; ++q) {
            const float4 w = row[q];
            acc[q*4+0] = fmaf(hj, w.x, acc[q*4+0]);
            acc[q*4+1] = fmaf(hj, w.y, acc[q*4+1]);
            acc[q*4+2] = fmaf(hj, w.z, acc[q*4+2]);
            acc[q*4+3] = fmaf(hj, w.w, acc[q*4+3]);
        }
    }
    float part = 0.0f;
#pragma unroll
    for (int k = 0; k < 16; ++k)
        part = fmaf(fmaxf(acc[k], 0.0f), __ldg(W3 + c * 16 + k), part);
    part += __shfl_down_sync(0xFFFFFFFFu, part, 2);
    part += __shfl_down_sync(0xFFFFFFFFu, part, 1);
    if (c == 0 && node < NNODES) g_nodes[node] = part + __ldg(b3);
}

// smem layout
#define TAB_BYTES  (NNODES * 8)                // 8208
#define Q_OFF      TAB_BYTES                   // + 1088 -> 9296
#define SNAP_OFF   9344                        // 2 x 512
#define COEFF_OFF  10368                       // 2 x 16384
#define CO_TILE    16384
#define OUT_OFF    43136                       // 2 x 12288
#define BUF_ARR    4096
#define BUF_P      (3 * BUF_ARR)
#define SMEM_TOTAL (OUT_OFF + 2 * BUF_P)       // 67712

extern __shared__ char smem_raw[];

__device__ __forceinline__ uint32_t smem_u32(const void* p) {
    uint32_t a;
    asm("{ .reg .u64 t; cvta.to.shared.u64 t, %1; cvt.u32.u64 %0, t; }"
        : "=r"(a) : "l"(p));
    return a;
}
__device__ __forceinline__ void sts128(uint32_t a, float x, float y, float z, float w) {
    asm volatile("st.shared.v4.f32 [%0], {%1, %2, %3, %4};"
                 :: "r"(a), "f"(x), "f"(y), "f"(z), "f"(w) : "memory");
}
__device__ __forceinline__ float4 lds128(uint32_t a) {
    float4 v;
    asm volatile("ld.shared.v4.f32 {%0, %1, %2, %3}, [%4];"
                 : "=f"(v.x), "=f"(v.y), "=f"(v.z), "=f"(v.w) : "r"(a));
    return v;
}
#define BAR_SYNC(id)   asm volatile("bar.sync %0, 64;"   :: "r"(id) : "memory")
#define BAR_ARRIVE(id) asm volatile("bar.arrive %0, 64;" :: "r"(id) : "memory")
// ids: 1,2 out_ready  3,4 out_free  5,6 coeff_ready  7,8 snap_ready+coeff_free

__device__ __forceinline__ float q_inc(float tf) {
    return __fmul_rn(__fmul_rn(__fmul_rn(SIGMA_C, __fmul_rn(DT_C, tf)),
                               0.125f), DT_C);
}

__global__ void __launch_bounds__(96, 1)
simulate_kernel(const float* __restrict__ Cv, const float* __restrict__ Kp,
                const float* __restrict__ jminp, float* __restrict__ out) {
    const int tid = threadIdx.x, lane = tid & 31, wid = tid >> 5;
    const float MAGIC = 12582912.0f;     // bits 0x4B400000

    float2* s_tab = reinterpret_cast<float2*>(smem_raw);
    float*  sQ    = reinterpret_cast<float*>(smem_raw + Q_OFF);

    for (int k = tid; k < TABN; k += 96) {
        const float nm = __ldg(g_nodes + k);
        const float nc = __ldg(g_nodes + k + 1);
        const float np = __ldg(g_nodes + k + 2);
        const float slope = 0.5f * (np - nm);
        s_tab[k] = make_float2(fmaf(-slope, (float)k, nc), slope * INVH_F);
    }
    if (tid == 0) {
        const float nm = __ldg(g_nodes + TABN - 1);
        const float nc = __ldg(g_nodes + TABN);
        const float np = __ldg(g_nodes + TABN + 1);
        const float slope = 0.5f * (np - nm);
        const float2 pe = make_float2(fmaf(-slope, (float)(TABN - 1), nc),
                                      slope * INVH_F);
        s_tab[TABN] = pe; s_tab[TABN + 1] = pe;
    }
    __syncthreads();

    const uint32_t tab32  = smem_u32(s_tab);
    const uint32_t tabC   = tab32 - 0x5A000000u;
    const uint32_t snap32 = smem_u32(smem_raw + SNAP_OFF);
    const uint32_t co32   = smem_u32(smem_raw + COEFF_OFF);
    const uint32_t buf32  = smem_u32(smem_raw + OUT_OFF);
    const int e0 = blockIdx.x * 32;

    if (wid == 1) {
        // ---------------- writer warp (unchanged, coalesced) ----------------
        BAR_ARRIVE(3); BAR_ARRIVE(4);
        float* oth0 = out + (size_t)e0 * NT_C;
        float* ore0 = oth0 + (size_t)B_C * NT_C;
        float* ocu0 = ore0 + (size_t)B_C * NT_C;
        float* oti0 = ocu0 + (size_t)B_C * NT_C;
        const int elw = lane >> 3, ch = lane & 7;
#pragma unroll
        for (int eg = 0; eg < 8; ++eg) {
            const int el = eg * 4 + elw;
            const size_t ro = (size_t)el * NT_C;
#pragma unroll
            for (int cc = 0; cc < 4; ++cc) {
                const int chunk = cc * 8 + ch;
                if (chunk < T_FROZEN / 4) {
                    const int t0 = chunk * 4;
                    const float tf = (float)t0;
                    float j0 = __fmul_rn(tf, 0.00175f);
                    if (t0 == 0) j0 = 1e-3f;
                    *reinterpret_cast<float4*>(oth0 + ro + t0) =
                        make_float4(0.f, 0.f, 0.f, 0.f);
                    *reinterpret_cast<float4*>(ore0 + ro + t0) =
                        make_float4(R0_C, R0_C, R0_C, R0_C);
                    *reinterpret_cast<float4*>(ocu0 + ro + t0) =
                        make_float4(j0, __fmul_rn(tf + 1.0f, 0.00175f),
                                    __fmul_rn(tf + 2.0f, 0.00175f),
                                    __fmul_rn(tf + 3.0f, 0.00175f));
                    *reinterpret_cast<float4*>(oti0 + ro + t0) =
                        make_float4(__fmul_rn(DT_C, tf),
                                    __fmul_rn(DT_C, tf + 1.0f),
                                    __fmul_rn(DT_C, tf + 2.0f),
                                    __fmul_rn(DT_C, tf + 3.0f));
                }
            }
        }
        for (int tile = 0; tile < NTILES_A; ++tile) {
            const int p = tile & 1;
            BAR_SYNC(1 + p);
            const uint32_t bp = buf32 + p * BUF_P;
            const int base = T_FROZEN + tile * TILE_S;
            const float tq0 = (float)(base + ch * 4);
            const float4 tv = make_float4(__fmul_rn(DT_C, tq0),
                                          __fmul_rn(DT_C, tq0 + 1.0f),
                                          __fmul_rn(DT_C, tq0 + 2.0f),
                                          __fmul_rn(DT_C, tq0 + 3.0f));
#pragma unroll
            for (int eg = 0; eg < 8; ++eg) {
                const int el = eg * 4 + elw;
                const uint32_t sa = bp + (uint32_t)el * 128u
                                  + (uint32_t)((ch ^ (el & 7)) << 4);
                const float4 a = lds128(sa + 0 * BUF_ARR);
                const float4 b = lds128(sa + 1 * BUF_ARR);
                const float4 c = lds128(sa + 2 * BUF_ARR);
                const size_t go = (size_t)el * NT_C + base + ch * 4;
                *reinterpret_cast<float4*>(oth0 + go) = a;
                *reinterpret_cast<float4*>(ore0 + go) = b;
                *reinterpret_cast<float4*>(ocu0 + go) = c;
                *reinterpret_cast<float4*>(oti0 + go) = tv;
            }
            BAR_ARRIVE(3 + p);
        }
        return;
    }

    // ---- warps 0 and 2: Q prefix (identical, redundant) + tstar ----
    {
        float Q = 0.0f;
        if (lane == 0) sQ[0] = 0.0f;
        for (int t = 1; t < QLEN; t += 4) {
            const float f0 = (float)t;
            const float i0 = q_inc(f0), i1 = q_inc(f0 + 1.0f);
            const float i2 = q_inc(f0 + 2.0f), i3 = q_inc(f0 + 3.0f);
            Q = __fadd_rn(Q, i0); if (lane == 0) sQ[t]     = Q;
            Q = __fadd_rn(Q, i1); if (lane == 0) sQ[t + 1] = Q;
            Q = __fadd_rn(Q, i2); if (lane == 0) sQ[t + 2] = Q;
            Q = __fadd_rn(Q, i3); if (lane == 0) sQ[t + 3] = Q;
        }
    }
    __syncwarp();

    const int e = e0 + lane;
    const float kk = __ldg(Kp + e);
    const double beta_d = 0.14 * 1.0 / (0.14 * 50.0 + 1.0);
    const float CQ = (float)pow(81.0 / (128.0 * beta_d), 1.0 / 3.0);
    const float Qmin = CQ * powf(kk, 4.0f / 3.0f);
    int lo = 0, hi = QLEN;
    while (hi - lo > 1) {
        const int mid = (lo + hi) >> 1;
        if (sQ[mid] <= Qmin) lo = mid; else hi = mid;
    }
    const int tstar = hi;
    const int tmax = __reduce_max_sync(0xFFFFFFFFu, tstar);
    int steadyTile = (tmax + 2 - T_FROZEN + TILE_S - 1) / TILE_S;
    if (steadyTile > NTILES_A) steadyTile = NTILES_A;
    if (steadyTile < 1) steadyTile = 1;
    const int nSteady = NTILES_A - steadyTile;

    if (wid == 2) {
        // ---------------- helper warp: coefficient stream ----------------
        const float t0sF = (float)(T_FROZEN + steadyTile * TILE_S);
        for (int i = 0; i < nSteady; ++i) {
            const int pc = i & 1;
            BAR_SYNC(7 + pc);                     // snap ready + coeff buf free
            const float4 sn = lds128(snap32 + pc * 512u + lane * 16u);
            const float den0 = sn.x, dif = sn.y, dd2 = sn.z, h0 = sn.w;
            const float tf = t0sF + (float)(i * TILE_S);
            const uint32_t wr = co32 + pc * CO_TILE + lane * 16u;
#pragma unroll 4
            for (int s = 0; s < TILE_S; ++s) {
                const float h  = h0 + (float)s;
                const float c2 = __fmul_rn(fmaf(h, h, h), 0.5f);
                float denE = fmaf(h, dif, den0);
                denE = fmaf(c2, dd2, denE);       // quadratic extrapolation
                float u;
                asm("rcp.approx.f32 %0, %1;" : "=f"(u) : "f"(denE));
                const float num = __fmul_rn(__fadd_rn(tf, (float)s), 0.014f);
                const float nu  = __fmul_rn(num, u);
                const float p   = __fmul_rn(nu, u);
                // j = nu(2 - D*u) = (2nu - p) - p*sigma*res,  D = 1 + sigma*res
                const float A  = __fadd_rn(__fadd_rn(nu, nu), -p);
                const float Bc = __fmul_rn(p, -SIGMA_C);
                const float m  = fmaf(nu, INVH_F, MAGIC);
                uint32_t bits = __float_as_uint(m);
                bits = min(bits, 0x4B400000u + (uint32_t)(TABN + 1));
                float c0v, c1v;
                asm volatile("ld.shared.v2.f32 {%0, %1}, [%2];"
                             : "=f"(c0v), "=f"(c1v) : "r"(bits * 8u + tabC));
                sts128(wr + (uint32_t)s * 512u, A, Bc, c0v, c1v);
            }
            BAR_ARRIVE(5 + pc);                   // coeff ready
        }
        return;
    }

    // ======================= compute warp =======================
    const float cv  = __ldg(Cv + e);
    const float jmn = __ldg(jminp + e);
    float res = R0_C, thk = 0.0f;
    const float cvdt = __fmul_rn(cv, DT_C);
    const float mjcC = __fmul_rn(-jmn, cvdt);

    // transition pipeline init at t0 = 112 (round-11 machinery)
    float u = 0.125f;
    float den_prev = 8.0f, dif_prev = 0.0f, ddif_c = 0.0f;
    const float nuA = __fmul_rn(__fmul_rn(112.0f, 0.014f), 0.125f);
    const float nuB = __fmul_rn(__fmul_rn(113.0f, 0.014f), 0.125f);
    float p0 = __fmul_rn(nuA, 0.125f), q0 = __fmul_rn(nuA, 2.0f);
    float p1 = __fmul_rn(nuB, 0.125f), q1 = __fmul_rn(nuB, 2.0f);
    float c00, c10, c01, c11;
#pragma unroll
    for (int k = 0; k < 2; ++k) {
        const float jk = __fmul_rn(112.0f + (float)k, 0.00175f);
        const float m  = fmaf(jk, INVH_F, MAGIC);
        uint32_t iu = __float_as_uint(m) & 0x3FFFFFu;
        iu = min(iu, (uint32_t)(TABN - 1));
        const float2 te = s_tab[iu];
        if (k == 0) { c00 = te.x; c10 = te.y; } else { c01 = te.x; c11 = te.y; }
    }
    float cvde0 = 0.0f, mjc0 = 0.0f, cvde1 = 0.0f, mjc1 = 0.0f;
    float tcp = 114.0f;

    const uint32_t row_l = buf32 + (uint32_t)lane * 128u;
    const uint32_t sw_l  = (uint32_t)((lane & 7) << 4);
    float sth[4], sre[4], scu[4];

    // -------- transition tiles (verified round-11 inline loop) --------
    for (int tile = 0; tile < steadyTile; ++tile) {
        const int p = tile & 1;
        BAR_SYNC(3 + p);
        const uint32_t bp = row_l + p * BUF_P;
        const int base = T_FROZEN + tile * TILE_S;
#pragma unroll
        for (int s = 0; s < TILE_S; ++s) {
            const float dd  = fmaf(dif_prev, 3.0f, den_prev);
            const float tN  = fmaf(dd, -u, 2.0f);
            const float u2  = __fmul_rn(u, tN);
            const float cu  = __fmul_rn(u2, 0.014f);
            const float nu2 = __fmul_rn(tcp, cu);
            const float p2  = __fmul_rn(nu2, u2);
            const float q2  = __fmul_rn(nu2, 2.0f);
            const float m   = fmaf(nu2, INVH_F, MAGIC);
            const uint32_t addr = __float_as_uint(m) * 8u + tabC;
            float na, nb;
            asm volatile("ld.shared.v2.f32 {%0, %1}, [%2];"
                         : "=f"(na), "=f"(nb) : "r"(addr));
            const bool a2 = (base + s + 2 >= tstar);
            const float cd2 = a2 ? cvdt : 0.0f;
            const float mj2 = a2 ? mjcC : 0.0f;
            u = u2; tcp += 1.0f;
            const float resin = res;
            const float den = fmaf(resin, SIGMA_C, 1.0f);
            const float jv  = fmaf(den, -p0, q0);
            const float rho = fmaf(jv, c10, c00);
            const float jd  = fmaf(jv, cvde0, mjc0);
            const float rc  = fmaf(rho, jd, resin);
            res = fmaxf(rc, R0_C);
            thk = fmaxf(thk + jd, 0.0f);
            sth[s & 3] = thk; sre[s & 3] = res; scu[s & 3] = jv;
            const float difn = __fadd_rn(den, -den_prev);
            ddif_c = __fadd_rn(difn, -dif_prev);
            dif_prev = difn; den_prev = den;
            p0 = p1; q0 = q1; p1 = p2; q1 = q2;
            c00 = c01; c10 = c11; c01 = na; c11 = nb;
            cvde0 = cvde1; mjc0 = mjc1; cvde1 = cd2; mjc1 = mj2;
            if ((s & 3) == 3) {
                const uint32_t co = (uint32_t)(((s >> 2) << 4)) ^ sw_l;
                sts128(bp + 0 * BUF_ARR + co, sth[0], sth[1], sth[2], sth[3]);
                sts128(bp + 1 * BUF_ARR + co, sre[0], sre[1], sre[2], sre[3]);
                sts128(bp + 2 * BUF_ARR + co, scu[0], scu[1], scu[2], scu[3]);
            }
        }
        BAR_ARRIVE(1 + p);
    }

    // initial snapshots (den0 = D before final update; h0=1 / h0=33)
    sts128(snap32 + lane * 16u,        den_prev, dif_prev, ddif_c, 1.0f);
    sts128(snap32 + 512u + lane * 16u, den_prev, dif_prev, ddif_c, 33.0f);
    BAR_ARRIVE(7); BAR_ARRIVE(8);

    // -------- steady tiles: coeff-driven, 2-deep coeff prefetch --------
    for (int k2 = 0; k2 < nSteady; ++k2) {
        const int po = (steadyTile + k2) & 1;
        const int pc = k2 & 1;
        BAR_SYNC(5 + pc);                         // coeffs ready
        BAR_SYNC(3 + po);                         // out buffer free
        const uint32_t bp = row_l + po * BUF_P;
        const uint32_t cp = co32 + pc * CO_TILE + lane * 16u;
        float4 cfa = lds128(cp);                  // step 0
        float4 cfb = lds128(cp + 512u);           // step 1
        float d29 = 0.f, d30 = 0.f, d31 = 0.f;
#pragma unroll
        for (int s = 0; s < TILE_S; ++s) {
            float4 cfn;
            if (s < TILE_S - 2)                   // prefetch step s+2
                cfn = lds128(cp + (uint32_t)(s + 2) * 512u);
            const float jv  = fmaf(res, cfa.y, cfa.x);   // j (Newton-folded)
            const float rho = fmaf(jv, cfa.w, cfa.z);
            const float jd  = fmaf(jv, cvdt, mjcC);
            const float rc  = fmaf(rho, jd, res);
            res = fmaxf(rc, R0_C);
            thk = fmaxf(thk + jd, 0.0f);
            sth[s & 3] = thk; sre[s & 3] = res; scu[s & 3] = jv;
            if (s == 29) d29 = fmaf(res, SIGMA_C, 1.0f);
            if (s == 30) d30 = fmaf(res, SIGMA_C, 1.0f);
            if (s == 31) d31 = fmaf(res, SIGMA_C, 1.0f);
            cfa = cfb; cfb = cfn;                 // rotate (renamed by unroll)
            if ((s & 3) == 3) {
                const uint32_t co = (uint32_t)(((s >> 2) << 4)) ^ sw_l;
                sts128(bp + 0 * BUF_ARR + co, sth[0], sth[1], sth[2], sth[3]);
                sts128(bp + 1 * BUF_ARR + co, sre[0], sre[1], sre[2], sre[3]);
                sts128(bp + 2 * BUF_ARR + co, scu[0], scu[1], scu[2], scu[3]);
            }
        }
        // snapshot for coeff build k2+2: den0 = D_{tile end}, h0 = 32
        const float dif = __fadd_rn(d31, -d30);
        const float dd2 = __fadd_rn(dif, -__fadd_rn(d30, -d29));
        sts128(snap32 + pc * 512u + lane * 16u, d31, dif, dd2, 32.0f);
        BAR_ARRIVE(7 + pc);
        BAR_ARRIVE(1 + po);
    }
}

extern "C" void kernel_launch(void* const* d_in, const int* in_sizes, int n_in,
                              void* d_out, int out_size) {
    const float* Cv = (const float*)d_in[0];
    const float* K  = (const float*)d_in[1];
    const float* jm = (const float*)d_in[2];
    const float* W1 = (const float*)d_in[3];
    const float* b1 = (const float*)d_in[4];
    const float* W2 = (const float*)d_in[5];
    const float* b2 = (const float*)d_in[6];
    const float* W3 = (const float*)d_in[7];
    const float* b3 = (const float*)d_in[8];
    float* out = (float*)d_out;

    build_nodes_kernel<<<NODE_BLOCKS, 128>>>(W1, b1, W2, b2, W3, b3);

    cudaFuncSetAttribute(simulate_kernel,
                         cudaFuncAttributeMaxDynamicSharedMemorySize, SMEM_TOTAL);
    simulate_kernel<<<B_C / 32, 96, SMEM_TOTAL>>>(Cv, K, jm, out);
}

// round 15
// speedup vs baseline: 1.8373x; 1.8373x over previous
#include <cuda_runtime.h>
#include <cstdint>
#include <math.h>

#define SIGMA_C 0.14f
#define R0_C    50.0f
#define DT_C    0.1f
#define NT_C    2000
#define B_C     4096

#define TABN   1024
#define NNODES (TABN + 2)
#define JMAX_C 3.5f
#define INVH_F ((float)TABN / JMAX_C)

#define T_FROZEN 112
#define TILE_S   32
#define NTILES_A ((NT_C - T_FROZEN) / TILE_S)    // 59
#define QLEN 272

__device__ float g_nodes[NNODES];

#define NODE_BLOCKS ((NNODES + 31) / 32)      // 33

__global__ void __launch_bounds__(128)
build_nodes_kernel(const float* __restrict__ W1, const float* __restrict__ b1,
                   const float* __restrict__ W2, const float* __restrict__ b2,
                   const float* __restrict__ W3, const float* __restrict__ b3) {
    const int tid = threadIdx.x;
    __shared__ float sW2[64 * 64];
    __shared__ float sh1[32][65];
    {
        const float4* src = reinterpret_cast<const float4*>(W2);
        float4* dst = reinterpret_cast<float4*>(sW2);
#pragma unroll
        for (int q = 0; q < 8; ++q) dst[tid + 128 * q] = __ldg(src + tid + 128 * q);
    }
    const int nl = tid >> 2, c = tid & 3;
    const int node = blockIdx.x * 32 + nl;
    const float x = (float)(node - 1) * (JMAX_C / (float)TABN);
#pragma unroll
    for (int k = 0; k < 16; ++k) {
        const int u = c * 16 + k;
        sh1[nl][u] = fmaxf(fmaf(x, __ldg(W1 + u), __ldg(b1 + u)), 0.0f);
    }
    __syncthreads();
    float acc[16];
#pragma unroll
    for (int k = 0; k < 16; ++k) acc[k] = __ldg(b2 + c * 16 + k);
#pragma unroll 4
    for (int j = 0; j < 64; ++j) {
        const float hj = sh1[nl][j];
        const float4* row = reinterpret_cast<const float4*>(sW2 + j * 64 + c * 16);
#pragma unroll
        for (int q = 0; q < 4; ++q) {
            const float4 w = row[q];
            acc[q*4+0] = fmaf(hj, w.x, acc[q*4+0]);
            acc[q*4+1] = fmaf(hj, w.y, acc[q*4+1]);
            acc[q*4+2] = fmaf(hj, w.z, acc[q*4+2]);
            acc[q*4+3] = fmaf(hj, w.w, acc[q*4+3]);
        }
    }
    float part = 0.0f;
#pragma unroll
    for (int k = 0; k < 16; ++k)
        part = fmaf(fmaxf(acc[k], 0.0f), __ldg(W3 + c * 16 + k), part);
    part += __shfl_down_sync(0xFFFFFFFFu, part, 2);
    part += __shfl_down_sync(0xFFFFFFFFu, part, 1);
    if (c == 0 && node < NNODES) g_nodes[node] = part + __ldg(b3);
}

// smem layout
#define TAB_BYTES  (NNODES * 8)                // 8208
#define Q_OFF      TAB_BYTES
#define BUF_OFF    9344                        // 128-aligned
#define BUF_ARR    4096                        // 32 rows * 128B
#define BUF_P      (3 * BUF_ARR)
#define SMEM_TOTAL (BUF_OFF + 2 * BUF_P)       // 33920

extern __shared__ char smem_raw[];

__device__ __forceinline__ uint32_t smem_u32(const void* p) {
    uint32_t a;
    asm("{ .reg .u64 t; cvta.to.shared.u64 t, %1; cvt.u32.u64 %0, t; }"
        : "=r"(a) : "l"(p));
    return a;
}
__device__ __forceinline__ void sts128(uint32_t a, float x, float y, float z, float w) {
    asm volatile("st.shared.v4.f32 [%0], {%1, %2, %3, %4};"
                 :: "r"(a), "f"(x), "f"(y), "f"(z), "f"(w) : "memory");
}
__device__ __forceinline__ float4 lds128(uint32_t a) {
    float4 v;
    asm volatile("ld.shared.v4.f32 {%0, %1, %2, %3}, [%4];"
                 : "=f"(v.x), "=f"(v.y), "=f"(v.z), "=f"(v.w) : "r"(a));
    return v;
}
#define BAR_SYNC(id)   asm volatile("bar.sync %0, 64;"   :: "r"(id) : "memory")
#define BAR_ARRIVE(id) asm volatile("bar.arrive %0, 64;" :: "r"(id) : "memory")

__device__ __forceinline__ float q_inc(float tf) {
    return __fmul_rn(__fmul_rn(__fmul_rn(SIGMA_C, __fmul_rn(DT_C, tf)),
                               0.125f), DT_C);
}

__global__ void __launch_bounds__(64, 1)
simulate_kernel(const float* __restrict__ Cv, const float* __restrict__ Kp,
                const float* __restrict__ jminp, float* __restrict__ out) {
    const int tid  = threadIdx.x;
    const int lane = tid & 31;
    const int wid  = tid >> 5;
    const float MAGIC = 12582912.0f;    // bits 0x4B400000

    float2* s_tab = reinterpret_cast<float2*>(smem_raw);
    float*  sQ    = reinterpret_cast<float*>(smem_raw + Q_OFF);

    {
        const int k0 = tid * (TABN / 64);
        float nm = __ldg(g_nodes + k0);
        float nc = __ldg(g_nodes + k0 + 1);
#pragma unroll 8
        for (int k = k0; k < k0 + TABN / 64; ++k) {
            const float np = __ldg(g_nodes + k + 2);
            const float slope = 0.5f * (np - nm);
            s_tab[k] = make_float2(fmaf(-slope, (float)k, nc), slope * INVH_F);
            nm = nc; nc = np;
        }
        if (tid == 63) {              // pad entries (affine extension)
            s_tab[TABN]     = s_tab[TABN - 1];
            s_tab[TABN + 1] = s_tab[TABN - 1];
        }
    }
    __syncthreads();

    const uint32_t tab32 = smem_u32(s_tab);
    const uint32_t tabC  = tab32 - 0x5A000000u;   // bits(MAGIC+idx)<<3 + tabC
    const uint32_t buf32 = smem_u32(smem_raw + BUF_OFF);
    const int e0 = blockIdx.x * 32;

    if (wid == 1) {
        // =================== writer warp (coalesced) ===================
        BAR_ARRIVE(3);
        BAR_ARRIVE(4);

        float* oth0 = out + (size_t)e0 * NT_C;
        float* ore0 = oth0 + (size_t)B_C * NT_C;
        float* ocu0 = ore0 + (size_t)B_C * NT_C;
        float* oti0 = ocu0 + (size_t)B_C * NT_C;

        const int elw = lane >> 3;
        const int ch  = lane & 7;

        // frozen region [0, 112): closed form, coalesced
#pragma unroll
        for (int eg = 0; eg < 8; ++eg) {
            const int el = eg * 4 + elw;
            const size_t ro = (size_t)el * NT_C;
#pragma unroll
            for (int cc = 0; cc < 4; ++cc) {
                const int chunk = cc * 8 + ch;
                if (chunk < T_FROZEN / 4) {
                    const int t0 = chunk * 4;
                    const float tf = (float)t0;
                    float j0 = __fmul_rn(tf, 0.00175f);
                    if (t0 == 0) j0 = 1e-3f;
                    *reinterpret_cast<float4*>(oth0 + ro + t0) =
                        make_float4(0.f, 0.f, 0.f, 0.f);
                    *reinterpret_cast<float4*>(ore0 + ro + t0) =
                        make_float4(R0_C, R0_C, R0_C, R0_C);
                    *reinterpret_cast<float4*>(ocu0 + ro + t0) =
                        make_float4(j0,
                                    __fmul_rn(tf + 1.0f, 0.00175f),
                                    __fmul_rn(tf + 2.0f, 0.00175f),
                                    __fmul_rn(tf + 3.0f, 0.00175f));
                    *reinterpret_cast<float4*>(oti0 + ro + t0) =
                        make_float4(__fmul_rn(DT_C, tf),
                                    __fmul_rn(DT_C, tf + 1.0f),
                                    __fmul_rn(DT_C, tf + 2.0f),
                                    __fmul_rn(DT_C, tf + 3.0f));
                }
            }
        }

        for (int tile = 0; tile < NTILES_A; ++tile) {
            const int p = tile & 1;
            BAR_SYNC(1 + p);
            const uint32_t bp = buf32 + p * BUF_P;
            const int base = T_FROZEN + tile * TILE_S;
            const float tq0 = (float)(base + ch * 4);
            const float4 tv = make_float4(__fmul_rn(DT_C, tq0),
                                          __fmul_rn(DT_C, tq0 + 1.0f),
                                          __fmul_rn(DT_C, tq0 + 2.0f),
                                          __fmul_rn(DT_C, tq0 + 3.0f));
#pragma unroll
            for (int eg = 0; eg < 8; ++eg) {
                const int el = eg * 4 + elw;
                const uint32_t sa = bp + (uint32_t)el * 128u
                                  + (uint32_t)((ch ^ (el & 7)) << 4);
                const float4 a = lds128(sa + 0 * BUF_ARR);
                const float4 b = lds128(sa + 1 * BUF_ARR);
                const float4 c = lds128(sa + 2 * BUF_ARR);
                const size_t go = (size_t)el * NT_C + base + ch * 4;
                *reinterpret_cast<float4*>(oth0 + go) = a;
                *reinterpret_cast<float4*>(ore0 + go) = b;
                *reinterpret_cast<float4*>(ocu0 + go) = c;
                *reinterpret_cast<float4*>(oti0 + go) = tv;
            }
            BAR_ARRIVE(3 + p);
        }
        return;
    }

    // =================== compute warp ===================
    {
        float Q = 0.0f;
        if (lane == 0) sQ[0] = 0.0f;
        for (int t = 1; t < QLEN; t += 4) {
            const float f0 = (float)t;
            const float i0 = q_inc(f0), i1 = q_inc(f0 + 1.0f);
            const float i2 = q_inc(f0 + 2.0f), i3 = q_inc(f0 + 3.0f);
            Q = __fadd_rn(Q, i0); if (lane == 0) sQ[t]     = Q;
            Q = __fadd_rn(Q, i1); if (lane == 0) sQ[t + 1] = Q;
            Q = __fadd_rn(Q, i2); if (lane == 0) sQ[t + 2] = Q;
            Q = __fadd_rn(Q, i3); if (lane == 0) sQ[t + 3] = Q;
        }
    }
    __syncwarp();

    const int e = e0 + lane;
    const float cv  = __ldg(Cv + e);
    const float kk  = __ldg(Kp + e);
    const float jmn = __ldg(jminp + e);

    const double beta_d = 0.14 * 1.0 / (0.14 * 50.0 + 1.0);
    const float CQ = (float)pow(81.0 / (128.0 * beta_d), 1.0 / 3.0);
    const float Qmin = CQ * powf(kk, 4.0f / 3.0f);     // [1.31, 5.69)

    int lo = 0, hi = QLEN;
    while (hi - lo > 1) {
        const int mid = (lo + hi) >> 1;
        if (sQ[mid] <= Qmin) lo = mid; else hi = mid;
    }
    const int tstar = hi;
    const int tmax  = __reduce_max_sync(0xFFFFFFFFu, tstar);

    int steadyTile = (tmax + 2 - T_FROZEN + TILE_S - 1) / TILE_S;
    if (steadyTile > NTILES_A) steadyTile = NTILES_A;

    float res = R0_C, thk = 0.0f;
    const float cvdt = __fmul_rn(cv, DT_C);
    const float mjcC = __fmul_rn(-jmn, cvdt);

    // pipeline init at t0 = 112 (round-11 machinery, verified)
    float u = 0.125f;
    float den_prev = 8.0f, dif_prev = 0.0f;
    const float nuA0 = __fmul_rn(__fmul_rn(112.0f, 0.014f), 0.125f);
    const float nuB0 = __fmul_rn(__fmul_rn(113.0f, 0.014f), 0.125f);
    float p0 = __fmul_rn(nuA0, 0.125f), q0 = __fmul_rn(nuA0, 2.0f);
    float p1 = __fmul_rn(nuB0, 0.125f), q1 = __fmul_rn(nuB0, 2.0f);
    float c00, c10, c01, c11;
#pragma unroll
    for (int k = 0; k < 2; ++k) {
        const float jk = __fmul_rn(112.0f + (float)k, 0.00175f);
        const float m  = fmaf(jk, INVH_F, MAGIC);
        uint32_t iu = __float_as_uint(m) & 0x3FFFFFu;
        iu = min(iu, (uint32_t)(TABN - 1));
        const float2 te = s_tab[iu];
        if (k == 0) { c00 = te.x; c10 = te.y; } else { c01 = te.x; c11 = te.y; }
    }
    float cvde0 = 0.0f, mjc0 = 0.0f, cvde1 = 0.0f, mjc1 = 0.0f;
    float tcp = 114.0f;

    const uint32_t row_l = buf32 + (uint32_t)lane * 128u;
    const uint32_t sw_l  = (uint32_t)((lane & 7) << 4);
    float sth[4], sre[4], scu[4];

    int tile = 0;
    // -------- transition tiles (byte-identical round-11 loop) --------
    for (; tile < steadyTile; ++tile) {
        const int p = tile & 1;
        BAR_SYNC(3 + p);
        const uint32_t bp = row_l + p * BUF_P;
        const int base = T_FROZEN + tile * TILE_S;
#pragma unroll
        for (int s = 0; s < TILE_S; ++s) {
            const float dd  = fmaf(dif_prev, 3.0f, den_prev);
            const float tN  = fmaf(dd, -u, 2.0f);
            const float u2  = __fmul_rn(u, tN);
            const float cu  = __fmul_rn(u2, 0.014f);
            const float nu2 = __fmul_rn(tcp, cu);
            const float p2  = __fmul_rn(nu2, u2);
            const float q2  = __fmul_rn(nu2, 2.0f);
            const float m   = fmaf(nu2, INVH_F, MAGIC);
            const uint32_t addr = __float_as_uint(m) * 8u + tabC;
            float na, nb;
            asm volatile("ld.shared.v2.f32 {%0, %1}, [%2];"
                         : "=f"(na), "=f"(nb) : "r"(addr));
            const bool a2 = (base + s + 2 >= tstar);
            const float cd2 = a2 ? cvdt : 0.0f;
            const float mj2 = a2 ? mjcC : 0.0f;
            u = u2; tcp += 1.0f;
            const float resin = res;
            const float den = fmaf(resin, SIGMA_C, 1.0f);
            const float jv  = fmaf(den, -p0, q0);
            const float rho = fmaf(jv, c10, c00);
            const float jd  = fmaf(jv, cvde0, mjc0);
            const float rc  = fmaf(rho, jd, resin);
            res = fmaxf(rc, R0_C);
            thk = fmaxf(thk + jd, 0.0f);
            sth[s & 3] = thk; sre[s & 3] = res; scu[s & 3] = jv;
            dif_prev = den - den_prev;
            den_prev = den;
            p0 = p1; q0 = q1; p1 = p2; q1 = q2;
            c00 = c01; c10 = c11; c01 = na; c11 = nb;
            cvde0 = cvde1; mjc0 = mjc1; cvde1 = cd2; mjc1 = mj2;
            if ((s & 3) == 3) {
                const uint32_t co = (uint32_t)(((s >> 2) << 4)) ^ sw_l;
                sts128(bp + 0 * BUF_ARR + co, sth[0], sth[1], sth[2], sth[3]);
                sts128(bp + 1 * BUF_ARR + co, sre[0], sre[1], sre[2], sre[3]);
                sts128(bp + 2 * BUF_ARR + co, scu[0], scu[1], scu[2], scu[3]);
            }
        }
        BAR_ARRIVE(1 + p);
    }

    // -------- steady tiles: paired prep (u Newton every 2 steps) --------
    // Entering: slots (p0,q0,c00,c10)=step t0s, (p1,q1,c01,c11)=t0s+1;
    // den_prev = den(t0s-1), dif_prev = 1-step diff, u ~ 1/den(t0s+1).
    float tslot = (float)(T_FROZEN + steadyTile * TILE_S + 2);
    for (; tile < NTILES_A; ++tile) {
        const int p = tile & 1;
        BAR_SYNC(3 + p);
        const uint32_t bp = row_l + p * BUF_P;
#pragma unroll
        for (int s = 0; s < TILE_S; s += 2) {
            // ---- prep pair slots (s+2, s+3); one Newton on extrapolated den
            const float dd  = fmaf(dif_prev, 3.5f, den_prev);   // ~den(s+2.5)
            const float tN  = fmaf(dd, -u, 2.0f);
            u = __fmul_rn(u, tN);
            const float numA = __fmul_rn(tslot, 0.014f);
            const float numB = fmaf(tslot, 0.014f, 0.014f);     // (tslot+1)*0.014
            const float nuA  = __fmul_rn(numA, u);
            const float nuB  = __fmul_rn(numB, u);
            const float pA   = __fmul_rn(nuA, u);
            const float pB   = __fmul_rn(nuB, u);
            const float qA   = __fmul_rn(nuA, 2.0f);
            const float qB   = __fmul_rn(nuB, 2.0f);
            const float mA   = fmaf(nuA, INVH_F, MAGIC);
            const float mB   = fmaf(nuB, INVH_F, MAGIC);
            const uint32_t aA = (__float_as_uint(mA) << 3) + tabC;  // alu pipe
            const uint32_t aB = (__float_as_uint(mB) << 3) + tabC;
            float nA0, nA1, nB0, nB1;
            asm volatile("ld.shared.v2.f32 {%0, %1}, [%2];"
                         : "=f"(nA0), "=f"(nA1) : "r"(aA));
            asm volatile("ld.shared.v2.f32 {%0, %1}, [%2];"
                         : "=f"(nB0), "=f"(nB1) : "r"(aB));
            tslot += 2.0f;
            // ---- step s (even)
            const float r0i  = res;
            const float den0 = fmaf(r0i, SIGMA_C, 1.0f);
            const float jv0  = fmaf(den0, -p0, q0);
            const float rho0 = fmaf(jv0, c10, c00);
            const float jd0  = fmaf(jv0, cvdt, mjcC);
            const float rc0  = fmaf(rho0, jd0, r0i);
            res = fmaxf(rc0, R0_C);
            thk = fmaxf(thk + jd0, 0.0f);
            sth[s & 3] = thk; sre[s & 3] = res; scu[s & 3] = jv0;
            // ---- step s+1 (odd)
            const float r1i  = res;
            const float den1 = fmaf(r1i, SIGMA_C, 1.0f);
            const float jv1  = fmaf(den1, -p1, q1);
            const float rho1 = fmaf(jv1, c11, c01);
            const float jd1  = fmaf(jv1, cvdt, mjcC);
            const float rc1  = fmaf(rho1, jd1, r1i);
            res = fmaxf(rc1, R0_C);
            thk = fmaxf(thk + jd1, 0.0f);
            sth[(s + 1) & 3] = thk; sre[(s + 1) & 3] = res;
            scu[(s + 1) & 3] = jv1;
            // ---- bookkeeping / rotate (renamed by unroll)
            dif_prev = __fadd_rn(den1, -den0);
            den_prev = den1;
            p0 = pA; q0 = qA; c00 = nA0; c10 = nA1;
            p1 = pB; q1 = qB; c01 = nB0; c11 = nB1;
            if ((s & 3) == 2) {
                const uint32_t co = (uint32_t)(((s >> 2) << 4)) ^ sw_l;
                sts128(bp + 0 * BUF_ARR + co, sth[0], sth[1], sth[2], sth[3]);
                sts128(bp + 1 * BUF_ARR + co, sre[0], sre[1], sre[2], sre[3]);
                sts128(bp + 2 * BUF_ARR + co, scu[0], scu[1], scu[2], scu[3]);
            }
        }
        BAR_ARRIVE(1 + p);
    }
}

extern "C" void kernel_launch(void* const* d_in, const int* in_sizes, int n_in,
                              void* d_out, int out_size) {
    const float* Cv = (const float*)d_in[0];
    const float* K  = (const float*)d_in[1];
    const float* jm = (const float*)d_in[2];
    const float* W1 = (const float*)d_in[3];
    const float* b1 = (const float*)d_in[4];
    const float* W2 = (const float*)d_in[5];
    const float* b2 = (const float*)d_in[6];
    const float* W3 = (const float*)d_in[7];
    const float* b3 = (const float*)d_in[8];
    float* out = (float*)d_out;

    build_nodes_kernel<<<NODE_BLOCKS, 128>>>(W1, b1, W2, b2, W3, b3);

    cudaFuncSetAttribute(simulate_kernel,
                         cudaFuncAttributeMaxDynamicSharedMemorySize, SMEM_TOTAL);
    simulate_kernel<<<B_C / 32, 64, SMEM_TOTAL>>>(Cv, K, jm, out);
}